// round 5
// baseline (speedup 1.0000x reference)
#include <cuda_runtime.h>
#include <math.h>

#define GRID_D    24
#define N_ANCH    13824           // 24*24*24
#define NV4       3456            // N_ANCH / 4
#define TPB       256
#define TOPK_N    60
#define NMS_TOPK  20
#define AVG_TOPN  7
#define SCORE_THR 0.15f
#define NMS_THR   0.05f
#define THRESH_L  2.2f
#define SPLIT     4
#define SEG_F4    864             // NV4 / SPLIT
#define SEG_CAP   512
#define CAND_MAX  2048            // SPLIT * SEG_CAP
#define MAX_B     256

// Per-image, per-part candidate scratch. Counts are overwritten every run.
__device__ unsigned long long g_keys[MAX_B][SPLIT][SEG_CAP];
__device__ int                g_cnt[MAX_B][SPLIT];

__device__ __forceinline__ unsigned long long make_key(float x, unsigned int idx) {
    float s = 1.0f / (1.0f + expf(-x));               // s in (0,1): float order == bit order
    return ((unsigned long long)__float_as_uint(s) << 32) |
           (unsigned long long)(0xFFFFFFFFu - idx);
}

// ---------------- Kernel 1: high-occupancy streaming scan ----------------
__global__ __launch_bounds__(TPB) void scan_kernel(const float* __restrict__ Cls)
{
    const int part = blockIdx.x;
    const int b    = blockIdx.y;
    const int tid  = threadIdx.x;
    const float4* cls4 = (const float4*)(Cls + (size_t)b * N_ANCH);

    __shared__ int s_pos;
    if (tid == 0) s_pos = 0;
    __syncthreads();

    const int base = part * SEG_F4;
    #pragma unroll
    for (int k = 0; k < 4; k++) {                     // 4*256 = 1024 >= 864
        int r = tid + k * TPB;
        if (r < SEG_F4) {
            int f = base + r;
            float4 x4 = cls4[f];
            float xs[4] = {x4.x, x4.y, x4.z, x4.w};
            #pragma unroll
            for (int c = 0; c < 4; c++) {
                if (xs[c] > THRESH_L) {
                    int pos = atomicAdd(&s_pos, 1);
                    if (pos < SEG_CAP)
                        g_keys[b][part][pos] = make_key(xs[c], (unsigned int)(4 * f + c));
                }
            }
        }
    }
    __syncthreads();
    if (tid == 0) g_cnt[b][part] = s_pos;             // raw count (may exceed cap -> fallback)
}

// ---------------- Kernel 2: per-image rank-select + NMS ----------------
__global__ __launch_bounds__(TPB) void nms_kernel(
    const float* __restrict__ Cls,
    const float* __restrict__ Shape,
    const float* __restrict__ Offset,
    float* __restrict__ Out)
{
    const int b   = blockIdx.x;
    const int tid = threadIdx.x;
    const float* shp = Shape  + (size_t)b * 3 * N_ANCH;
    const float* off = Offset + (size_t)b * 3 * N_ANCH;

    __shared__ unsigned long long keys[CAND_MAX];
    __shared__ int                s_cand;
    // field-major det storage: conflict-free for lane-varying box index
    __shared__ float              detT[8][64];     // [field][rank]
    __shared__ float              loT[3][64], hiT[3][64], volT[64];
    __shared__ float              iouS[TOPK_N][TOPK_N];

    // zero-init (only matters on the impossible <60-candidates path)
    if (tid < 64) {
        #pragma unroll
        for (int f = 0; f < 8; f++) detT[f][tid] = 0.0f;
        #pragma unroll
        for (int d = 0; d < 3; d++) { loT[d][tid] = 0.0f; hiT[d][tid] = 0.0f; }
        volT[tid] = 0.0f;
    }

    // ---- compact segments ----
    int cnts[SPLIT], offs[SPLIT];
    int C = 0; bool overflow = false;
    #pragma unroll
    for (int p = 0; p < SPLIT; p++) {
        int c = g_cnt[b][p];
        if (c > SEG_CAP) { overflow = true; c = SEG_CAP; }
        cnts[p] = c; offs[p] = C; C += c;
    }
    #pragma unroll
    for (int p = 0; p < SPLIT; p++) {
        for (int i = tid; i < cnts[p]; i += TPB)
            keys[offs[p] + i] = g_keys[b][p][i];
    }
    __syncthreads();

    // ---- deterministic fallback: rescan this image with adaptive threshold ----
    if (overflow || C < TOPK_N) {
        const float4* cls4 = (const float4*)(Cls + (size_t)b * N_ANCH);
        float L = THRESH_L, stepL = 0.5f;
        int dir = 0;
        for (int attempt = 0; attempt < 24; attempt++) {
            if (tid == 0) s_cand = 0;
            __syncthreads();
            for (int f = tid; f < NV4; f += TPB) {
                float4 x4 = cls4[f];
                float xs[4] = {x4.x, x4.y, x4.z, x4.w};
                #pragma unroll
                for (int c = 0; c < 4; c++) {
                    if (xs[c] > L) {
                        int pos = atomicAdd(&s_cand, 1);
                        if (pos < CAND_MAX)
                            keys[pos] = make_key(xs[c], (unsigned int)(4 * f + c));
                    }
                }
            }
            __syncthreads();
            C = s_cand;
            if (C >= TOPK_N && C <= CAND_MAX) break;
            if (C < TOPK_N) { if (dir > 0) stepL *= 0.5f; L -= stepL; dir = -1; }
            else            { if (dir < 0) stepL *= 0.5f; L += stepL; dir = +1; }
            __syncthreads();
        }
        C = min(C, CAND_MAX);
    }

    // ---- rank-based top-60 selection + fused gather (keys are all distinct) ----
    for (int i = tid; i < C; i += TPB) {
        unsigned long long myKey = keys[i];
        int rank = 0;
        int j = 0;
        for (; j + 4 <= C; j += 4) {
            rank += (keys[j]     > myKey);
            rank += (keys[j + 1] > myKey);
            rank += (keys[j + 2] > myKey);
            rank += (keys[j + 3] > myKey);
        }
        for (; j < C; j++) rank += (keys[j] > myKey);

        if (rank < TOPK_N) {
            unsigned int idx = 0xFFFFFFFFu - (unsigned int)(myKey & 0xFFFFFFFFull);
            float s = __uint_as_float((unsigned int)(myKey >> 32));
            int iz = (int)idx / (GRID_D * GRID_D);
            int iy = ((int)idx / GRID_D) % GRID_D;
            int ix = (int)idx % GRID_D;
            float cz = ((float)iz + off[0 * N_ANCH + idx]) * 4.0f;
            float cy = ((float)iy + off[1 * N_ANCH + idx]) * 4.0f;
            float cx = ((float)ix + off[2 * N_ANCH + idx]) * 4.0f;
            float sz = shp[0 * N_ANCH + idx];
            float sy = shp[1 * N_ANCH + idx];
            float sx = shp[2 * N_ANCH + idx];
            detT[0][rank] = 1.0f; detT[1][rank] = s;
            detT[2][rank] = cz;   detT[3][rank] = cy; detT[4][rank] = cx;
            detT[5][rank] = sz;   detT[6][rank] = sy; detT[7][rank] = sx;
            loT[0][rank] = cz - 0.5f * sz; hiT[0][rank] = cz + 0.5f * sz;
            loT[1][rank] = cy - 0.5f * sy; hiT[1][rank] = cy + 0.5f * sy;
            loT[2][rank] = cx - 0.5f * sx; hiT[2][rank] = cx + 0.5f * sx;
            volT[rank]   = sz * sy * sx;
        }
    }
    __syncthreads();

    // ---- 60x60 IoU matrix (conflict-free reads) ----
    for (int p = tid; p < TOPK_N * TOPK_N; p += TPB) {
        int i = p / TOPK_N, j = p % TOPK_N;
        float w0 = fminf(hiT[0][i], hiT[0][j]) - fmaxf(loT[0][i], loT[0][j]);
        float w1 = fminf(hiT[1][i], hiT[1][j]) - fmaxf(loT[1][i], loT[1][j]);
        float w2 = fminf(hiT[2][i], hiT[2][j]) - fmaxf(loT[2][i], loT[2][j]);
        float inter = fmaxf(w0, 0.0f) * fmaxf(w1, 0.0f) * fmaxf(w2, 0.0f);
        iouS[i][j] = inter / (volT[i] + volT[j] - inter);
    }
    __syncthreads();

    // ---- 20-step greedy averaging NMS, entirely in warp 0 ----
    if (tid < 32) {
        const int lane = tid;
        const int r0 = lane, r1 = lane + 32;
        const int f  = lane & 7;          // field this lane accumulates
        const int t2 = lane >> 3;         // handles selected slots t2 and t2+4

        bool v0 = (detT[1][r0] > SCORE_THR);
        bool v1 = (r1 < TOPK_N) && (detT[1][r1] > SCORE_THR);
        unsigned int b0 = __ballot_sync(0xFFFFFFFFu, v0);
        unsigned int b1 = __ballot_sync(0xFFFFFFFFu, v1);
        unsigned long long validM =
            (unsigned long long)b0 | ((unsigned long long)b1 << 32);
        unsigned long long supp = 0ull;

        for (int step = 0; step < NMS_TOPK; step++) {
            unsigned long long avail = validM & ~supp;
            bool any = (avail != 0ull);
            int  idx = any ? (__ffsll((long long)avail) - 1) : 0;

            bool m0 = any && ((avail >> r0) & 1ull) &&
                      (iouS[idx][r0] > NMS_THR || r0 == idx);
            bool m1 = any && (r1 < TOPK_N) && ((avail >> r1) & 1ull) &&
                      (iouS[idx][r1] > NMS_THR || r1 == idx);
            unsigned int mb0 = __ballot_sync(0xFFFFFFFFu, m0);
            unsigned int mb1 = __ballot_sync(0xFFFFFFFFu, m1);
            unsigned long long matched =
                (unsigned long long)mb0 | ((unsigned long long)mb1 << 32);
            supp |= matched;

            int cnt  = __popcll(matched);
            int topn = min(cnt, AVG_TOPN);

            // parallel average: this lane fetches selected slots t2 and t2+4 of field f
            float sum = 0.0f;
            #pragma unroll
            for (int k = 0; k < 2; k++) {
                int t = t2 + 4 * k;
                if (t < topn) {
                    unsigned long long mm = matched;
                    #pragma unroll
                    for (int q = 0; q < AVG_TOPN; q++)
                        if (q < t) mm &= mm - 1ull;
                    int jj = __ffsll((long long)mm) - 1;
                    sum += detT[f][jj];
                }
            }
            sum += __shfl_xor_sync(0xFFFFFFFFu, sum, 8);
            sum += __shfl_xor_sync(0xFFFFFFFFu, sum, 16);

            if (lane < 8) {
                float r;
                if (!any) {
                    r = -1.0f;
                } else if (topn > 1) {
                    r = sum / (float)topn;
                    if (lane == 0) r = 1.0f;
                    if (lane == 1) r = detT[1][idx];
                } else {
                    r = detT[lane][idx];
                }
                Out[((size_t)b * NMS_TOPK + step) * 8 + lane] = r;
            }
        }
    }
}

extern "C" void kernel_launch(void* const* d_in, const int* in_sizes, int n_in,
                              void* d_out, int out_size) {
    const float* Cls    = (const float*)d_in[0];
    const float* Shape  = (const float*)d_in[1];
    const float* Offset = (const float*)d_in[2];
    float*       Out    = (float*)d_out;
    int B = in_sizes[0] / N_ANCH;
    dim3 g1(SPLIT, B);
    scan_kernel<<<g1, TPB>>>(Cls);
    nms_kernel<<<B, TPB>>>(Cls, Shape, Offset, Out);
}

// round 6
// speedup vs baseline: 1.2058x; 1.2058x over previous
#include <cuda_runtime.h>
#include <math.h>

#define GRID_D    24
#define N_ANCH    13824           // 24*24*24
#define NV4       3456            // N_ANCH / 4
#define TPB       256
#define TOPK_N    60
#define NMS_TOPK  20
#define AVG_TOPN  7
#define SCORE_THR 0.15f
#define NMS_THR   0.05f
#define THRESH_L  2.3f
#define SPLIT     4
#define SEG_F4    864             // NV4 / SPLIT
#define SEG_CAP   512
#define CAND_MAX  2048            // SPLIT * SEG_CAP
#define MAX_B     256

// Per-image, per-part candidate scratch. Counts are overwritten every run.
__device__ unsigned long long g_keys[MAX_B][SPLIT][SEG_CAP];
__device__ int                g_cnt[MAX_B][SPLIT];   // [b][p], 16B-aligned per image

__device__ __forceinline__ unsigned long long make_key(float x, unsigned int idx) {
    float s = 1.0f / (1.0f + expf(-x));               // s in (0,1): float order == bit order
    return ((unsigned long long)__float_as_uint(s) << 32) |
           (unsigned long long)(0xFFFFFFFFu - idx);
}

// ---------------- Kernel 1: high-occupancy streaming scan ----------------
__global__ __launch_bounds__(TPB) void scan_kernel(const float* __restrict__ Cls)
{
    const int part = blockIdx.x;
    const int b    = blockIdx.y;
    const int tid  = threadIdx.x;
    const float4* cls4 = (const float4*)(Cls + (size_t)b * N_ANCH);

    __shared__ int s_pos;
    if (tid == 0) s_pos = 0;
    __syncthreads();

    const int base = part * SEG_F4;
    #pragma unroll
    for (int k = 0; k < 4; k++) {                     // 4*256 = 1024 >= 864
        int r = tid + k * TPB;
        if (r < SEG_F4) {
            int f = base + r;
            float4 x4 = cls4[f];
            float xs[4] = {x4.x, x4.y, x4.z, x4.w};
            #pragma unroll
            for (int c = 0; c < 4; c++) {
                if (xs[c] > THRESH_L) {
                    int pos = atomicAdd(&s_pos, 1);
                    if (pos < SEG_CAP)
                        g_keys[b][part][pos] = make_key(xs[c], (unsigned int)(4 * f + c));
                }
            }
        }
    }
    __syncthreads();
    if (tid == 0) g_cnt[b][part] = s_pos;             // raw count (may exceed cap -> fallback)
}

// ---------------- Kernel 2: per-image rank-select + mask-NMS ----------------
__global__ __launch_bounds__(TPB) void nms_kernel(
    const float* __restrict__ Cls,
    const float* __restrict__ Shape,
    const float* __restrict__ Offset,
    float* __restrict__ Out)
{
    const int b   = blockIdx.x;
    const int tid = threadIdx.x;
    const float* shp = Shape  + (size_t)b * 3 * N_ANCH;
    const float* off = Offset + (size_t)b * 3 * N_ANCH;

    __shared__ unsigned long long keys[CAND_MAX];
    __shared__ int                s_cand;
    __shared__ float              detT[8][64];     // [field][rank], conflict-free
    __shared__ float              loT[3][64], hiT[3][64], volT[64];
    __shared__ unsigned int       maskLo[TOPK_N], maskHi[TOPK_N];

    // one broadcast 16B load for the 4 segment counts (issued first)
    const int4 c4 = *(const int4*)&g_cnt[b][0];

    // zero-init det fields (matters only on the impossible <60-candidate path)
    if (tid < 64) {
        #pragma unroll
        for (int f = 0; f < 8; f++) detT[f][tid] = 0.0f;
        #pragma unroll
        for (int d = 0; d < 3; d++) { loT[d][tid] = 0.0f; hiT[d][tid] = 0.0f; }
        volT[tid] = 0.0f;
    }

    // ---- compact segments ----
    int cnts[SPLIT], offs[SPLIT];
    {
        int raw[SPLIT] = {c4.x, c4.y, c4.z, c4.w};
        int acc = 0;
        #pragma unroll
        for (int p = 0; p < SPLIT; p++) {
            int c = raw[p] > SEG_CAP ? SEG_CAP : raw[p];
            cnts[p] = c; offs[p] = acc; acc += c;
        }
    }
    int C = offs[SPLIT - 1] + cnts[SPLIT - 1];
    bool overflow = (c4.x > SEG_CAP) | (c4.y > SEG_CAP) | (c4.z > SEG_CAP) | (c4.w > SEG_CAP);

    #pragma unroll
    for (int p = 0; p < SPLIT; p++) {
        for (int i = tid; i < cnts[p]; i += TPB)
            keys[offs[p] + i] = g_keys[b][p][i];
    }
    __syncthreads();

    // ---- deterministic fallback: rescan this image with adaptive threshold ----
    if (overflow || C < TOPK_N) {
        const float4* cls4 = (const float4*)(Cls + (size_t)b * N_ANCH);
        float L = THRESH_L, stepL = 0.5f;
        int dir = 0;
        for (int attempt = 0; attempt < 24; attempt++) {
            if (tid == 0) s_cand = 0;
            __syncthreads();
            for (int f = tid; f < NV4; f += TPB) {
                float4 x4 = cls4[f];
                float xs[4] = {x4.x, x4.y, x4.z, x4.w};
                #pragma unroll
                for (int c = 0; c < 4; c++) {
                    if (xs[c] > L) {
                        int pos = atomicAdd(&s_cand, 1);
                        if (pos < CAND_MAX)
                            keys[pos] = make_key(xs[c], (unsigned int)(4 * f + c));
                    }
                }
            }
            __syncthreads();
            C = s_cand;
            if (C >= TOPK_N && C <= CAND_MAX) break;
            if (C < TOPK_N) { if (dir > 0) stepL *= 0.5f; L -= stepL; dir = -1; }
            else            { if (dir < 0) stepL *= 0.5f; L += stepL; dir = +1; }
            __syncthreads();
        }
        C = min(C, CAND_MAX);
    }

    // ---- rank-based top-60 selection with prefetched gather ----
    // Gather loads depend only on idx, so issue them BEFORE the rank loop;
    // DRAM latency overlaps the C compares.
    for (int i = tid; i < C; i += TPB) {
        unsigned long long myKey = keys[i];
        unsigned int idx = 0xFFFFFFFFu - (unsigned int)(myKey & 0xFFFFFFFFull);
        float oz = off[0 * N_ANCH + idx];
        float oy = off[1 * N_ANCH + idx];
        float ox = off[2 * N_ANCH + idx];
        float sz = shp[0 * N_ANCH + idx];
        float sy = shp[1 * N_ANCH + idx];
        float sx = shp[2 * N_ANCH + idx];

        int rank = 0;
        int j = 0;
        for (; j + 4 <= C; j += 4) {
            rank += (keys[j]     > myKey);
            rank += (keys[j + 1] > myKey);
            rank += (keys[j + 2] > myKey);
            rank += (keys[j + 3] > myKey);
        }
        for (; j < C; j++) rank += (keys[j] > myKey);

        if (rank < TOPK_N) {
            float s = __uint_as_float((unsigned int)(myKey >> 32));
            int iz = (int)idx / (GRID_D * GRID_D);
            int iy = ((int)idx / GRID_D) % GRID_D;
            int ix = (int)idx % GRID_D;
            float cz = ((float)iz + oz) * 4.0f;
            float cy = ((float)iy + oy) * 4.0f;
            float cx = ((float)ix + ox) * 4.0f;
            detT[0][rank] = 1.0f; detT[1][rank] = s;
            detT[2][rank] = cz;   detT[3][rank] = cy; detT[4][rank] = cx;
            detT[5][rank] = sz;   detT[6][rank] = sy; detT[7][rank] = sx;
            loT[0][rank] = cz - 0.5f * sz; hiT[0][rank] = cz + 0.5f * sz;
            loT[1][rank] = cy - 0.5f * sy; hiT[1][rank] = cy + 0.5f * sy;
            loT[2][rank] = cx - 0.5f * sx; hiT[2][rank] = cx + 0.5f * sx;
            volT[rank]   = sz * sy * sx;
        }
    }
    __syncthreads();

    // ---- neighbor bitmasks: warp w handles rows i = w + 8*r ----
    // bit j of mask[i] = (iou(i,j) > NMS_THR) | (j == i), via multiply-form compare.
    {
        const int w    = tid >> 5;
        const int lane = tid & 31;
        for (int i = w; i < TOPK_N; i += 8) {
            float l0 = loT[0][i], h0 = hiT[0][i];
            float l1 = loT[1][i], h1 = hiT[1][i];
            float l2 = loT[2][i], h2 = hiT[2][i];
            float vi = volT[i];
            unsigned int bits0, bits1;
            {
                int j = lane;
                float w0 = fminf(h0, hiT[0][j]) - fmaxf(l0, loT[0][j]);
                float w1 = fminf(h1, hiT[1][j]) - fmaxf(l1, loT[1][j]);
                float w2 = fminf(h2, hiT[2][j]) - fmaxf(l2, loT[2][j]);
                float inter = fmaxf(w0, 0.0f) * fmaxf(w1, 0.0f) * fmaxf(w2, 0.0f);
                bool hit = (inter * (1.0f + NMS_THR) > NMS_THR * (vi + volT[j])) | (j == i);
                bits0 = __ballot_sync(0xFFFFFFFFu, hit);
            }
            {
                int j = lane + 32;
                bool hit = false;
                if (j < TOPK_N) {
                    float w0 = fminf(h0, hiT[0][j]) - fmaxf(l0, loT[0][j]);
                    float w1 = fminf(h1, hiT[1][j]) - fmaxf(l1, loT[1][j]);
                    float w2 = fminf(h2, hiT[2][j]) - fmaxf(l2, loT[2][j]);
                    float inter = fmaxf(w0, 0.0f) * fmaxf(w1, 0.0f) * fmaxf(w2, 0.0f);
                    hit = (inter * (1.0f + NMS_THR) > NMS_THR * (vi + volT[j])) | (j == i);
                }
                bits1 = __ballot_sync(0xFFFFFFFFu, hit);
            }
            if (lane == 0) { maskLo[i] = bits0; maskHi[i] = bits1; }
        }
    }
    __syncthreads();

    // ---- 20-step greedy averaging NMS, warp 0, no ballots in loop ----
    if (tid < 32) {
        const int lane = tid;
        const int r0 = lane, r1 = lane + 32;
        const int f  = lane & 7;          // field this lane accumulates
        const int t2 = lane >> 3;         // handles selected slots t2 and t2+4

        bool v0 = (detT[1][r0] > SCORE_THR);
        bool v1 = (r1 < TOPK_N) && (detT[1][r1] > SCORE_THR);
        unsigned int b0 = __ballot_sync(0xFFFFFFFFu, v0);
        unsigned int b1 = __ballot_sync(0xFFFFFFFFu, v1);
        unsigned long long validM =
            (unsigned long long)b0 | ((unsigned long long)b1 << 32);
        unsigned long long supp = 0ull;

        for (int step = 0; step < NMS_TOPK; step++) {
            unsigned long long avail = validM & ~supp;
            bool any = (avail != 0ull);
            int  idx = any ? (__ffsll((long long)avail) - 1) : 0;

            unsigned long long m64 =
                (unsigned long long)maskLo[idx] | ((unsigned long long)maskHi[idx] << 32);
            unsigned long long matched = any ? (avail & m64) : 0ull;
            supp |= matched;

            int cnt  = __popcll(matched);
            int topn = min(cnt, AVG_TOPN);

            // parallel average: this lane fetches selected slots t2 and t2+4 of field f
            float sum = 0.0f;
            #pragma unroll
            for (int k = 0; k < 2; k++) {
                int t = t2 + 4 * k;
                if (t < topn) {
                    unsigned long long mm = matched;
                    #pragma unroll
                    for (int q = 0; q < AVG_TOPN; q++)
                        if (q < t) mm &= mm - 1ull;
                    int jj = __ffsll((long long)mm) - 1;
                    sum += detT[f][jj];
                }
            }
            sum += __shfl_xor_sync(0xFFFFFFFFu, sum, 8);
            sum += __shfl_xor_sync(0xFFFFFFFFu, sum, 16);

            if (lane < 8) {
                float r;
                if (!any) {
                    r = -1.0f;
                } else if (topn > 1) {
                    r = sum / (float)topn;
                    if (lane == 0) r = 1.0f;
                    if (lane == 1) r = detT[1][idx];
                } else {
                    r = detT[lane][idx];
                }
                Out[((size_t)b * NMS_TOPK + step) * 8 + lane] = r;
            }
        }
    }
}

extern "C" void kernel_launch(void* const* d_in, const int* in_sizes, int n_in,
                              void* d_out, int out_size) {
    const float* Cls    = (const float*)d_in[0];
    const float* Shape  = (const float*)d_in[1];
    const float* Offset = (const float*)d_in[2];
    float*       Out    = (float*)d_out;
    int B = in_sizes[0] / N_ANCH;
    dim3 g1(SPLIT, B);
    scan_kernel<<<g1, TPB>>>(Cls);
    nms_kernel<<<B, TPB>>>(Cls, Shape, Offset, Out);
}